// round 15
// baseline (speedup 1.0000x reference)
#include <cuda_runtime.h>

#define KBATCH 64
#define NN 1024
#define DIN 16
#define H1D 4
#define DOUT 8
#define FC1D 54

typedef unsigned long long ull;

// ---------------- scratch (static device memory) ----------------
__device__ unsigned g_adjQ[NN * 256];      // byte masks: word(i,q,lane) byte b = adj[i][(4q+b)*32+lane] ? 0xFF : 0
__device__ ull g_h1q[2 * KBATCH * NN];     // layer1 h pairs, SoA: [q][k*N+n]
__device__ ull g_h2q[4 * KBATCH * NN];     // layer2 h pairs, SoA
__device__ float g_f1u1[KBATCH * NN];      // layer1 u_i = e^{-0.99 f1}
__device__ ull g_f2p1[KBATCH * NN];        // layer1 {e^f2, e^{0.01 f2}}
__device__ float g_f1u2[KBATCH * NN];      // layer2 u_i = e^{-0.99 f1}
__device__ ull g_f2p2[KBATCH * NN];        // layer2 {e^f2, e^{0.01 f2}}
__device__ ull g_g4[KBATCH * NN * 4];      // relu(gat2) pairs == [K][8192] floats
__device__ float g_xp[512 * FC1D * 16];    // fc1 partials [dchunk*4+kq][c][k%16]

// ---------------- f32x2 helpers ----------------
__device__ __forceinline__ ull mul2(ull a, ull b) {
    ull r; asm("mul.rn.f32x2 %0,%1,%2;" : "=l"(r) : "l"(a), "l"(b)); return r;
}
__device__ __forceinline__ ull fma2(ull a, ull b, ull c) {
    ull r; asm("fma.rn.f32x2 %0,%1,%2,%3;" : "=l"(r) : "l"(a), "l"(b), "l"(c)); return r;
}
__device__ __forceinline__ ull add2(ull a, ull b) {
    ull r; asm("add.rn.f32x2 %0,%1,%2;" : "=l"(r) : "l"(a), "l"(b)); return r;
}
__device__ __forceinline__ float lo2(ull v) { return __uint_as_float((unsigned)v); }
__device__ __forceinline__ float hi2(ull v) { return __uint_as_float((unsigned)(v >> 32)); }
__device__ __forceinline__ ull pk(float x, float y) {
    return (ull)__float_as_uint(x) | ((ull)__float_as_uint(y) << 32);
}
__device__ __forceinline__ ull pku(unsigned x, unsigned y) {
    ull r; asm("mov.b64 %0,{%1,%2};" : "=l"(r) : "r"(x), "r"(y)); return r;
}
__device__ __forceinline__ ull bcast2(unsigned v) {
    ull r; asm("mov.b64 %0,{%1,%1};" : "=l"(r) : "r"(v)); return r;
}
__device__ __forceinline__ ull shfl2(ull v, int o) {
    unsigned l = (unsigned)v, h = (unsigned)(v >> 32);
    l = __shfl_xor_sync(0xffffffffu, l, o);
    h = __shfl_xor_sync(0xffffffffu, h, o);
    return (ull)l | ((ull)h << 32);
}

// ---------------- prologue: pack adj bytes + prep1 ----------------
__global__ void prologue_kernel(const int* __restrict__ adj,
                                const float* __restrict__ X,
                                const float* __restrict__ W1,
                                const float* __restrict__ a1) {
    __shared__ float w[DIN * H1D];
    __shared__ float a[2 * H1D];
    int b = blockIdx.x, t = threadIdx.x;
    if (b < 128) {
        int warp = t >> 5, lane = t & 31;
        int i = b * 8 + warp;
#pragma unroll
        for (int q = 0; q < 8; q++) {
            unsigned word = 0;
#pragma unroll
            for (int bb = 0; bb < 4; bb++) {
                int v = adj[i * NN + (4 * q + bb) * 32 + lane];
                word |= (v > 0 ? 0xFFu : 0u) << (8 * bb);
            }
            g_adjQ[i * 256 + q * 32 + lane] = word;
        }
    } else {
        if (t < DIN * H1D) w[t] = W1[t];
        if (t < 2 * H1D) a[t] = a1[t];
        __syncthreads();
        int kn = (b - 128) * 256 + t;
        const float4* x4 = reinterpret_cast<const float4*>(X) + kn * 4;
        float h[H1D] = {0.f, 0.f, 0.f, 0.f};
#pragma unroll
        for (int q = 0; q < 4; q++) {
            float4 xv = x4[q];
            float xs[4] = {xv.x, xv.y, xv.z, xv.w};
#pragma unroll
            for (int d = 0; d < 4; d++)
#pragma unroll
                for (int c = 0; c < H1D; c++)
                    h[c] += xs[d] * w[(q * 4 + d) * H1D + c];
        }
        float f1 = 0.f, f2 = 0.f;
#pragma unroll
        for (int c = 0; c < H1D; c++) { f1 += h[c] * a[c]; f2 += h[c] * a[H1D + c]; }
        g_h1q[kn] = pk(h[0], h[1]);
        g_h1q[KBATCH * NN + kn] = pk(h[2], h[3]);
        g_f1u1[kn] = __expf(-0.99f * f1);
        g_f2p1[kn] = pk(__expf(f2), __expf(0.01f * f2));
    }
}

// ---------------- attention layer 1: 512 thr; row-factored; distributed reduction; fuses prep2 ----------------
__global__ void __launch_bounds__(512, 1)
attn1_kernel(const float* __restrict__ W2, const float* __restrict__ a2) {
    constexpr int CH = 4;
    constexpr int RPW = 8;
    constexpr int NPAIR = RPW / 2;
    __shared__ float fsx[NN];                 // x_j = e^{f2_j}
    __shared__ ull fsyd[NN];                  // {y_j, y_j}
    __shared__ ull vsd[CH][NN];               // {h_c, h_c}
    __shared__ float w2s[H1D * DOUT + 2 * DOUT];
    __shared__ float hsc[16][RPW][CH];        // [warp][row][ch] epilogue scratch

    const int k = blockIdx.y;
    const int tid = threadIdx.x;

    const ull* fk = g_f2p1 + k * NN;
#pragma unroll
    for (int idx = tid; idx < NN; idx += 512) {
        ull f = fk[idx];
        fsx[idx] = lo2(f);
        fsyd[idx] = bcast2((unsigned)(f >> 32));
        ull u0 = g_h1q[k * NN + idx];
        ull u1 = g_h1q[KBATCH * NN + k * NN + idx];
        vsd[0][idx] = bcast2((unsigned)u0);
        vsd[1][idx] = bcast2((unsigned)(u0 >> 32));
        vsd[2][idx] = bcast2((unsigned)u1);
        vsd[3][idx] = bcast2((unsigned)(u1 >> 32));
    }
    if (tid < H1D * DOUT + 2 * DOUT)
        w2s[tid] = (tid < H1D * DOUT) ? W2[tid] : a2[tid - H1D * DOUT];
    __syncthreads();

    const int warp = tid >> 5, lane = tid & 31;
    const int i0 = blockIdx.x * (16 * RPW) + warp * RPW;

    ull u2[NPAIR], z2[NPAIR], v[NPAIR * CH];   // v[p*4+c] = {sum_r0 h_c, sum_r1 h_c}
#pragma unroll
    for (int p = 0; p < NPAIR; p++) {
        u2[p] = pk(g_f1u1[k * NN + i0 + 2 * p], g_f1u1[k * NN + i0 + 2 * p + 1]);
        z2[p] = 0ull;
#pragma unroll
        for (int c = 0; c < CH; c++) v[p * 4 + c] = 0ull;
    }

#pragma unroll 2
    for (int g = 0; g < 8; g++) {
        unsigned aw[RPW];
#pragma unroll
        for (int r = 0; r < RPW; r++)
            aw[r] = g_adjQ[(i0 + r) * 256 + g * 32 + lane];
#pragma unroll
        for (int bb = 0; bb < 4; bb++) {
            const int j = (4 * g + bb) * 32 + lane;
            const unsigned sel = bb * 0x1111u;
            float xj = fsx[j];
            ull yd = fsyd[j];
            ull hd[CH];
#pragma unroll
            for (int c = 0; c < CH; c++) hd[c] = vsd[c][j];
#pragma unroll
            for (int p = 0; p < NPAIR; p++) {
                ull t2 = mul2(u2[p], yd);
                float pl = fmaxf(xj, lo2(t2));
                float ph = fmaxf(xj, hi2(t2));
                unsigned pu0 = __float_as_uint(pl) & __byte_perm(aw[2 * p], 0, sel);
                unsigned pu1 = __float_as_uint(ph) & __byte_perm(aw[2 * p + 1], 0, sel);
                ull p2 = pku(pu0, pu1);
                z2[p] = add2(z2[p], p2);
#pragma unroll
                for (int c = 0; c < CH; c++) v[p * 4 + c] = fma2(p2, hd[c], v[p * 4 + c]);
            }
        }
    }

    // z: naive butterfly (all lanes get totals)
#pragma unroll
    for (int o = 16; o; o >>= 1)
#pragma unroll
        for (int p = 0; p < NPAIR; p++) z2[p] = add2(z2[p], shfl2(z2[p], o));

    // v[16]: level 16 naive, then distributed (lane l & l+16 end with slot l&15)
#pragma unroll
    for (int i = 0; i < 16; i++) v[i] = add2(v[i], shfl2(v[i], 16));
#pragma unroll
    for (int s = 0; s < 4; s++) {
        const int o = 8 >> s;
        const int nv = 16 >> s;
        const bool hi = (lane & o) != 0;
#pragma unroll
        for (int i = 0; i < nv / 2; i++) {
            ull send = hi ? v[i] : v[i + nv / 2];
            ull recv = shfl2(send, o);
            ull keep = hi ? v[i + nv / 2] : v[i];
            v[i] = add2(keep, recv);
        }
    }

    // lane l<16 holds slot m=l: p=m>>2, c=m&3 -> {row2p, row2p+1} channel c
    if (lane < 16) {
        const int p = lane >> 2, c = lane & 3;
        ull zp = z2[p];
        float z0 = lo2(zp), z1 = hi2(zp);
        float inv0 = (z0 > 0.f) ? 1.f / z0 : 0.f;
        float inv1 = (z1 > 0.f) ? 1.f / z1 : 0.f;
        hsc[warp][2 * p][c]     = fmaxf(lo2(v[0]) * inv0, 0.f);
        hsc[warp][2 * p + 1][c] = fmaxf(hi2(v[0]) * inv1, 0.f);
    }
    __syncwarp();

    if (lane < RPW) {
        float hv0 = hsc[warp][lane][0];
        float hv1 = hsc[warp][lane][1];
        float hv2 = hsc[warp][lane][2];
        float hv3 = hsc[warp][lane][3];
        const int gi = k * NN + i0 + lane;
        float hh[DOUT];
#pragma unroll
        for (int o = 0; o < DOUT; o++)
            hh[o] = hv0 * w2s[o] + hv1 * w2s[DOUT + o] + hv2 * w2s[2 * DOUT + o] + hv3 * w2s[3 * DOUT + o];
        float f1 = 0.f, f2 = 0.f;
#pragma unroll
        for (int o = 0; o < DOUT; o++) {
            f1 += hh[o] * w2s[H1D * DOUT + o];
            f2 += hh[o] * w2s[H1D * DOUT + DOUT + o];
        }
#pragma unroll
        for (int q = 0; q < 4; q++)
            g_h2q[q * (KBATCH * NN) + gi] = pk(hh[2 * q], hh[2 * q + 1]);
        g_f1u2[gi] = __expf(-0.99f * f1);
        g_f2p2[gi] = pk(__expf(f2), __expf(0.01f * f2));
    }
}

// ---------------- attention layer 2: 512 thr; row-factored; distributed reduction ----------------
__global__ void __launch_bounds__(512, 1)
attn2_kernel() {
    constexpr int NP = 4;
    constexpr int RPW = 8;
    __shared__ float fsx[NN];
    __shared__ ull fsyd[NN];
    __shared__ ull vs[NP][NN];

    const int k = blockIdx.y;
    const int tid = threadIdx.x;

    const ull* fk = g_f2p2 + k * NN;
#pragma unroll
    for (int idx = tid; idx < NN; idx += 512) {
        ull f = fk[idx];
        fsx[idx] = lo2(f);
        fsyd[idx] = bcast2((unsigned)(f >> 32));
    }
#pragma unroll
    for (int idx = tid; idx < NN * NP; idx += 512) {
        int q = idx >> 10, j = idx & (NN - 1);
        vs[q][j] = g_h2q[q * (KBATCH * NN) + k * NN + j];
    }
    __syncthreads();

    const int warp = tid >> 5, lane = tid & 31;
    const int i0 = blockIdx.x * (16 * RPW) + warp * RPW;

    ull u2[RPW / 2];
    ull z2[RPW / 2];
    ull v[RPW * NP];                    // v[r*4+q] = {c_{2q}, c_{2q+1}} sums for row r
#pragma unroll
    for (int p = 0; p < RPW / 2; p++) {
        u2[p] = pk(g_f1u2[k * NN + i0 + 2 * p], g_f1u2[k * NN + i0 + 2 * p + 1]);
        z2[p] = 0ull;
    }
#pragma unroll
    for (int m = 0; m < RPW * NP; m++) v[m] = 0ull;

#pragma unroll 2
    for (int g = 0; g < 8; g++) {
        unsigned aw[RPW];
#pragma unroll
        for (int r = 0; r < RPW; r++)
            aw[r] = g_adjQ[(i0 + r) * 256 + g * 32 + lane];
#pragma unroll
        for (int bb = 0; bb < 4; bb++) {
            const int j = (4 * g + bb) * 32 + lane;
            const unsigned sel = bb * 0x1111u;
            float xj = fsx[j];
            ull yd = fsyd[j];
            ull hv[NP];
#pragma unroll
            for (int q = 0; q < NP; q++) hv[q] = vs[q][j];
#pragma unroll
            for (int p = 0; p < RPW / 2; p++) {
                ull t2 = mul2(u2[p], yd);
                float pl = fmaxf(xj, lo2(t2));
                float ph = fmaxf(xj, hi2(t2));
                unsigned pu0 = __float_as_uint(pl) & __byte_perm(aw[2 * p], 0, sel);
                unsigned pu1 = __float_as_uint(ph) & __byte_perm(aw[2 * p + 1], 0, sel);
                z2[p] = add2(z2[p], pku(pu0, pu1));
                ull pp0 = bcast2(pu0);
                ull pp1 = bcast2(pu1);
#pragma unroll
                for (int q = 0; q < NP; q++) {
                    v[(2 * p) * 4 + q]     = fma2(pp0, hv[q], v[(2 * p) * 4 + q]);
                    v[(2 * p + 1) * 4 + q] = fma2(pp1, hv[q], v[(2 * p + 1) * 4 + q]);
                }
            }
        }
    }

    // z: naive butterfly
#pragma unroll
    for (int o = 16; o; o >>= 1)
#pragma unroll
        for (int p = 0; p < RPW / 2; p++) z2[p] = add2(z2[p], shfl2(z2[p], o));

    // v[32]: fully distributed butterfly -> lane l holds slot l
#pragma unroll
    for (int s = 0; s < 5; s++) {
        const int o = 16 >> s;
        const int nv = 32 >> s;
        const bool hi = (lane & o) != 0;
#pragma unroll
        for (int i = 0; i < nv / 2; i++) {
            ull send = hi ? v[i] : v[i + nv / 2];
            ull recv = shfl2(send, o);
            ull keep = hi ? v[i + nv / 2] : v[i];
            v[i] = add2(keep, recv);
        }
    }

    // lane l: r = l>>2, q = l&3; coalesced STG.64 across the warp
    {
        const int r = lane >> 2, q = lane & 3;
        ull zp = z2[r >> 1];
        float Z = (r & 1) ? hi2(zp) : lo2(zp);
        float invz = (Z > 0.f) ? 1.f / Z : 0.f;
        const int gi = k * NN + i0 + r;
        g_g4[gi * 4 + q] = pk(fmaxf(lo2(v[0]) * invz, 0.f),
                              fmaxf(hi2(v[0]) * invz, 0.f));
    }
}

// ---------------- head: fc1 split-K GEMM (128 d-chunks x 4 k-quarters), R12 form ----------------
#define FBLK 64
__global__ void __launch_bounds__(256) head_fc1_kernel(const float* __restrict__ fc1w) {
    __shared__ float gs[16][FBLK + 1];
    __shared__ float ws[FBLK][64];
    const int t = threadIdx.x;
    const int d0 = blockIdx.x * FBLK;
    const int k0 = blockIdx.y * 16;
    const float* gg = reinterpret_cast<const float*>(g_g4);

#pragma unroll
    for (int idx = t; idx < 16 * (FBLK / 4); idx += 256) {
        int k = idx / (FBLK / 4), v = idx % (FBLK / 4);
        float4 x = *reinterpret_cast<const float4*>(gg + (k0 + k) * (NN * DOUT) + d0 + 4 * v);
        gs[k][4 * v + 0] = x.x; gs[k][4 * v + 1] = x.y;
        gs[k][4 * v + 2] = x.z; gs[k][4 * v + 3] = x.w;
    }
    for (int idx = t; idx < FBLK * FC1D; idx += 256) {
        int d = idx / FC1D, c = idx % FC1D;
        ws[d][c] = fc1w[d0 * FC1D + idx];
    }
    __syncthreads();

    const int k = t & 15;
    const int cg = t >> 4;
    ull acc[2] = {0ull, 0ull};

#pragma unroll 8
    for (int d = 0; d < FBLK; d++) {
        ull g2 = bcast2(__float_as_uint(gs[k][d]));
        const ull* w2 = reinterpret_cast<const ull*>(&ws[d][cg * 4]);
        acc[0] = fma2(g2, w2[0], acc[0]);
        acc[1] = fma2(g2, w2[1], acc[1]);
    }

    float* dst = g_xp + (size_t)(blockIdx.x * 4 + blockIdx.y) * FC1D * 16;
    const int cbase = cg * 4;
#pragma unroll
    for (int q = 0; q < 2; q++) {
        int c = cbase + 2 * q;
        if (c < FC1D)     dst[c * 16 + k] = lo2(acc[q]);
        if (c + 1 < FC1D) dst[(c + 1) * 16 + k] = hi2(acc[q]);
    }
}

// ---------------- head_out: reduce partials + bias/relu + GEMV (R12 form) ----------------
__global__ void __launch_bounds__(256) head_out_kernel(const float* __restrict__ fc1b,
                                                       const float* __restrict__ outw,
                                                       const float* __restrict__ outb,
                                                       float* __restrict__ out) {
    __shared__ float part[4][FC1D];
    __shared__ float xs[FC1D];
    const int k = blockIdx.y;
    const int t = threadIdx.x;
    const int kq = k >> 4, kk = k & 15;

    if (t < 4 * FC1D) {
        const int c = t % FC1D, q = t / FC1D;
        float s = 0.f;
#pragma unroll 8
        for (int d = q * 32; d < q * 32 + 32; d++)
            s += g_xp[((size_t)(d * 4 + kq) * FC1D + c) * 16 + kk];
        part[q][c] = s;
    }
    __syncthreads();
    if (t < FC1D)
        xs[t] = fmaxf(part[0][t] + part[1][t] + part[2][t] + part[3][t] + fc1b[t], 0.f);
    __syncthreads();

    const int n = blockIdx.x * 256 + t;
    float s = outb[n];
#pragma unroll
    for (int c2 = 0; c2 < FC1D; c2++) s += xs[c2] * outw[c2 * NN + n];
    out[k * NN + n] = s;
}

// ---------------- launch ----------------
extern "C" void kernel_launch(void* const* d_in, const int* in_sizes, int n_in,
                              void* d_out, int out_size) {
    const float* X    = (const float*)d_in[0];
    const int*   adj  = (const int*)d_in[1];
    const float* W1   = (const float*)d_in[2];
    const float* a1   = (const float*)d_in[3];
    const float* W2   = (const float*)d_in[4];
    const float* a2   = (const float*)d_in[5];
    const float* fc1w = (const float*)d_in[6];
    const float* fc1b = (const float*)d_in[7];
    const float* outw = (const float*)d_in[8];
    const float* outb = (const float*)d_in[9];
    float* out = (float*)d_out;

    prologue_kernel<<<384, 256>>>(adj, X, W1, a1);
    {
        dim3 grid(NN / 128, KBATCH);    // 512 thr, 16 warps, 128 rows/block
        attn1_kernel<<<grid, 512>>>(W2, a2);
        attn2_kernel<<<grid, 512>>>();
    }
    {
        dim3 gridf((NN * DOUT) / FBLK, 4);   // 128 d-chunks x 4 k-quarters
        head_fc1_kernel<<<gridf, 256>>>(fc1w);
    }
    {
        dim3 grid(NN / 256, KBATCH);
        head_out_kernel<<<grid, 256>>>(fc1b, outw, outb, out);
    }
}

// round 16
// speedup vs baseline: 1.1464x; 1.1464x over previous
#include <cuda_runtime.h>

#define KBATCH 64
#define NN 1024
#define DIN 16
#define H1D 4
#define DOUT 8
#define FC1D 54

typedef unsigned long long ull;

// ---------------- scratch (static device memory) ----------------
__device__ unsigned g_adjQ[NN * 256];      // byte masks: word(i,q,lane) byte b = adj[i][(4q+b)*32+lane] ? 0xFF : 0
__device__ ull g_h1q[2 * KBATCH * NN];     // layer1 h pairs, SoA: [q][k*N+n]
__device__ ull g_h2q[4 * KBATCH * NN];     // layer2 h pairs, SoA
__device__ float g_f1u1[KBATCH * NN];      // layer1 u_i = e^{-0.99 f1}
__device__ ull g_f2p1[KBATCH * NN];        // layer1 {e^f2, e^{0.01 f2}}
__device__ float g_f1u2[KBATCH * NN];      // layer2 u_i = e^{-0.99 f1}
__device__ ull g_f2p2[KBATCH * NN];        // layer2 {e^f2, e^{0.01 f2}}
__device__ ull g_g4[KBATCH * NN * 4];      // relu(gat2) pairs == [K][8192] floats
__device__ float g_xp[512 * FC1D * 16];    // fc1 partials [dchunk*4+kq][c][k%16]

// ---------------- f32x2 helpers ----------------
__device__ __forceinline__ ull mul2(ull a, ull b) {
    ull r; asm("mul.rn.f32x2 %0,%1,%2;" : "=l"(r) : "l"(a), "l"(b)); return r;
}
__device__ __forceinline__ ull fma2(ull a, ull b, ull c) {
    ull r; asm("fma.rn.f32x2 %0,%1,%2,%3;" : "=l"(r) : "l"(a), "l"(b), "l"(c)); return r;
}
__device__ __forceinline__ ull add2(ull a, ull b) {
    ull r; asm("add.rn.f32x2 %0,%1,%2;" : "=l"(r) : "l"(a), "l"(b)); return r;
}
__device__ __forceinline__ float lo2(ull v) { return __uint_as_float((unsigned)v); }
__device__ __forceinline__ float hi2(ull v) { return __uint_as_float((unsigned)(v >> 32)); }
__device__ __forceinline__ ull pk(float x, float y) {
    return (ull)__float_as_uint(x) | ((ull)__float_as_uint(y) << 32);
}
__device__ __forceinline__ ull pku(unsigned x, unsigned y) {
    ull r; asm("mov.b64 %0,{%1,%2};" : "=l"(r) : "r"(x), "r"(y)); return r;
}
__device__ __forceinline__ ull bcast2(unsigned v) {
    ull r; asm("mov.b64 %0,{%1,%1};" : "=l"(r) : "r"(v)); return r;
}
__device__ __forceinline__ ull shfl2(ull v, int o) {
    unsigned l = (unsigned)v, h = (unsigned)(v >> 32);
    l = __shfl_xor_sync(0xffffffffu, l, o);
    h = __shfl_xor_sync(0xffffffffu, h, o);
    return (ull)l | ((ull)h << 32);
}

// ---------------- prologue: pack adj bytes + prep1 ----------------
__global__ void prologue_kernel(const int* __restrict__ adj,
                                const float* __restrict__ X,
                                const float* __restrict__ W1,
                                const float* __restrict__ a1) {
    __shared__ float w[DIN * H1D];
    __shared__ float a[2 * H1D];
    int b = blockIdx.x, t = threadIdx.x;
    if (b < 128) {
        int warp = t >> 5, lane = t & 31;
        int i = b * 8 + warp;
#pragma unroll
        for (int q = 0; q < 8; q++) {
            unsigned word = 0;
#pragma unroll
            for (int bb = 0; bb < 4; bb++) {
                int v = adj[i * NN + (4 * q + bb) * 32 + lane];
                word |= (v > 0 ? 0xFFu : 0u) << (8 * bb);
            }
            g_adjQ[i * 256 + q * 32 + lane] = word;
        }
    } else {
        if (t < DIN * H1D) w[t] = W1[t];
        if (t < 2 * H1D) a[t] = a1[t];
        __syncthreads();
        int kn = (b - 128) * 256 + t;
        const float4* x4 = reinterpret_cast<const float4*>(X) + kn * 4;
        float h[H1D] = {0.f, 0.f, 0.f, 0.f};
#pragma unroll
        for (int q = 0; q < 4; q++) {
            float4 xv = x4[q];
            float xs[4] = {xv.x, xv.y, xv.z, xv.w};
#pragma unroll
            for (int d = 0; d < 4; d++)
#pragma unroll
                for (int c = 0; c < H1D; c++)
                    h[c] += xs[d] * w[(q * 4 + d) * H1D + c];
        }
        float f1 = 0.f, f2 = 0.f;
#pragma unroll
        for (int c = 0; c < H1D; c++) { f1 += h[c] * a[c]; f2 += h[c] * a[H1D + c]; }
        g_h1q[kn] = pk(h[0], h[1]);
        g_h1q[KBATCH * NN + kn] = pk(h[2], h[3]);
        g_f1u1[kn] = __expf(-0.99f * f1);
        g_f2p1[kn] = pk(__expf(f2), __expf(0.01f * f2));
    }
}

// ---------------- attention layer 1: row-factored; distributed reduction; fuses prep2 ----------------
__global__ void __launch_bounds__(256, 2)
attn1_kernel(const float* __restrict__ W2, const float* __restrict__ a2) {
    constexpr int CH = 4;
    constexpr int RPW = 8;
    constexpr int NPAIR = RPW / 2;
    __shared__ float fsx[NN];                 // x_j = e^{f2_j}
    __shared__ ull fsyd[NN];                  // {y_j, y_j}
    __shared__ ull vsd[CH][NN];               // {h_c, h_c}
    __shared__ float w2s[H1D * DOUT + 2 * DOUT];
    __shared__ float hsc[8][RPW][CH];         // [warp][row][ch] epilogue scratch

    const int k = blockIdx.y;
    const int tid = threadIdx.x;

    const ull* fk = g_f2p1 + k * NN;
#pragma unroll
    for (int idx = tid; idx < NN; idx += 256) {
        ull f = fk[idx];
        fsx[idx] = lo2(f);
        fsyd[idx] = bcast2((unsigned)(f >> 32));
        ull u0 = g_h1q[k * NN + idx];
        ull u1 = g_h1q[KBATCH * NN + k * NN + idx];
        vsd[0][idx] = bcast2((unsigned)u0);
        vsd[1][idx] = bcast2((unsigned)(u0 >> 32));
        vsd[2][idx] = bcast2((unsigned)u1);
        vsd[3][idx] = bcast2((unsigned)(u1 >> 32));
    }
    if (tid < H1D * DOUT + 2 * DOUT)
        w2s[tid] = (tid < H1D * DOUT) ? W2[tid] : a2[tid - H1D * DOUT];
    __syncthreads();

    const int warp = tid >> 5, lane = tid & 31;
    const int i0 = blockIdx.x * (8 * RPW) + warp * RPW;

    ull u2[NPAIR], z2[NPAIR], v[NPAIR * CH];   // v[p*4+c] = {sum_r0 h_c, sum_r1 h_c}
#pragma unroll
    for (int p = 0; p < NPAIR; p++) {
        u2[p] = pk(g_f1u1[k * NN + i0 + 2 * p], g_f1u1[k * NN + i0 + 2 * p + 1]);
        z2[p] = 0ull;
#pragma unroll
        for (int c = 0; c < CH; c++) v[p * 4 + c] = 0ull;
    }

#pragma unroll 2
    for (int g = 0; g < 8; g++) {
        unsigned aw[RPW];
#pragma unroll
        for (int r = 0; r < RPW; r++)
            aw[r] = g_adjQ[(i0 + r) * 256 + g * 32 + lane];
#pragma unroll
        for (int bb = 0; bb < 4; bb++) {
            const int j = (4 * g + bb) * 32 + lane;
            const unsigned sel = bb * 0x1111u;
            float xj = fsx[j];
            ull yd = fsyd[j];
            ull hd[CH];
#pragma unroll
            for (int c = 0; c < CH; c++) hd[c] = vsd[c][j];
#pragma unroll
            for (int p = 0; p < NPAIR; p++) {
                ull t2 = mul2(u2[p], yd);
                float pl = fmaxf(xj, lo2(t2));
                float ph = fmaxf(xj, hi2(t2));
                unsigned pu0 = __float_as_uint(pl) & __byte_perm(aw[2 * p], 0, sel);
                unsigned pu1 = __float_as_uint(ph) & __byte_perm(aw[2 * p + 1], 0, sel);
                ull p2 = pku(pu0, pu1);
                z2[p] = add2(z2[p], p2);
#pragma unroll
                for (int c = 0; c < CH; c++) v[p * 4 + c] = fma2(p2, hd[c], v[p * 4 + c]);
            }
        }
    }

    // z: naive butterfly (all lanes get totals)
#pragma unroll
    for (int o = 16; o; o >>= 1)
#pragma unroll
        for (int p = 0; p < NPAIR; p++) z2[p] = add2(z2[p], shfl2(z2[p], o));

    // v[16]: level 16 naive, then distributed (lane l & l+16 end with slot l&15)
#pragma unroll
    for (int i = 0; i < 16; i++) v[i] = add2(v[i], shfl2(v[i], 16));
#pragma unroll
    for (int s = 0; s < 4; s++) {
        const int o = 8 >> s;
        const int nv = 16 >> s;
        const bool hi = (lane & o) != 0;
#pragma unroll
        for (int i = 0; i < nv / 2; i++) {
            ull send = hi ? v[i] : v[i + nv / 2];
            ull recv = shfl2(send, o);
            ull keep = hi ? v[i + nv / 2] : v[i];
            v[i] = add2(keep, recv);
        }
    }

    // lane l<16 holds slot m=l: p=m>>2, c=m&3 -> {row2p, row2p+1} channel c
    if (lane < 16) {
        const int p = lane >> 2, c = lane & 3;
        ull zp = z2[p];
        float z0 = lo2(zp), z1 = hi2(zp);
        float inv0 = (z0 > 0.f) ? 1.f / z0 : 0.f;
        float inv1 = (z1 > 0.f) ? 1.f / z1 : 0.f;
        hsc[warp][2 * p][c]     = fmaxf(lo2(v[0]) * inv0, 0.f);
        hsc[warp][2 * p + 1][c] = fmaxf(hi2(v[0]) * inv1, 0.f);
    }
    __syncwarp();

    if (lane < RPW) {
        float hv0 = hsc[warp][lane][0];
        float hv1 = hsc[warp][lane][1];
        float hv2 = hsc[warp][lane][2];
        float hv3 = hsc[warp][lane][3];
        const int gi = k * NN + i0 + lane;
        float hh[DOUT];
#pragma unroll
        for (int o = 0; o < DOUT; o++)
            hh[o] = hv0 * w2s[o] + hv1 * w2s[DOUT + o] + hv2 * w2s[2 * DOUT + o] + hv3 * w2s[3 * DOUT + o];
        float f1 = 0.f, f2 = 0.f;
#pragma unroll
        for (int o = 0; o < DOUT; o++) {
            f1 += hh[o] * w2s[H1D * DOUT + o];
            f2 += hh[o] * w2s[H1D * DOUT + DOUT + o];
        }
#pragma unroll
        for (int q = 0; q < 4; q++)
            g_h2q[q * (KBATCH * NN) + gi] = pk(hh[2 * q], hh[2 * q + 1]);
        g_f1u2[gi] = __expf(-0.99f * f1);
        g_f2p2[gi] = pk(__expf(f2), __expf(0.01f * f2));
    }
}

// ---------------- attention layer 2: row-factored; distributed reduction ----------------
__global__ void __launch_bounds__(256, 2)
attn2_kernel() {
    constexpr int NP = 4;
    constexpr int RPW = 8;
    __shared__ float fsx[NN];
    __shared__ ull fsyd[NN];
    __shared__ ull vs[NP][NN];

    const int k = blockIdx.y;
    const int tid = threadIdx.x;

    const ull* fk = g_f2p2 + k * NN;
#pragma unroll
    for (int idx = tid; idx < NN; idx += 256) {
        ull f = fk[idx];
        fsx[idx] = lo2(f);
        fsyd[idx] = bcast2((unsigned)(f >> 32));
    }
#pragma unroll
    for (int idx = tid; idx < NN * NP; idx += 256) {
        int q = idx >> 10, j = idx & (NN - 1);
        vs[q][j] = g_h2q[q * (KBATCH * NN) + k * NN + j];
    }
    __syncthreads();

    const int warp = tid >> 5, lane = tid & 31;
    const int i0 = blockIdx.x * (8 * RPW) + warp * RPW;

    ull u2[RPW / 2];
    ull z2[RPW / 2];
    ull v[RPW * NP];                    // v[r*4+q] = {c_{2q}, c_{2q+1}} sums for row r
#pragma unroll
    for (int p = 0; p < RPW / 2; p++) {
        u2[p] = pk(g_f1u2[k * NN + i0 + 2 * p], g_f1u2[k * NN + i0 + 2 * p + 1]);
        z2[p] = 0ull;
    }
#pragma unroll
    for (int m = 0; m < RPW * NP; m++) v[m] = 0ull;

#pragma unroll 2
    for (int g = 0; g < 8; g++) {
        unsigned aw[RPW];
#pragma unroll
        for (int r = 0; r < RPW; r++)
            aw[r] = g_adjQ[(i0 + r) * 256 + g * 32 + lane];
#pragma unroll
        for (int bb = 0; bb < 4; bb++) {
            const int j = (4 * g + bb) * 32 + lane;
            const unsigned sel = bb * 0x1111u;
            float xj = fsx[j];
            ull yd = fsyd[j];
            ull hv[NP];
#pragma unroll
            for (int q = 0; q < NP; q++) hv[q] = vs[q][j];
#pragma unroll
            for (int p = 0; p < RPW / 2; p++) {
                ull t2 = mul2(u2[p], yd);
                float pl = fmaxf(xj, lo2(t2));
                float ph = fmaxf(xj, hi2(t2));
                unsigned pu0 = __float_as_uint(pl) & __byte_perm(aw[2 * p], 0, sel);
                unsigned pu1 = __float_as_uint(ph) & __byte_perm(aw[2 * p + 1], 0, sel);
                z2[p] = add2(z2[p], pku(pu0, pu1));
                ull pp0 = bcast2(pu0);
                ull pp1 = bcast2(pu1);
#pragma unroll
                for (int q = 0; q < NP; q++) {
                    v[(2 * p) * 4 + q]     = fma2(pp0, hv[q], v[(2 * p) * 4 + q]);
                    v[(2 * p + 1) * 4 + q] = fma2(pp1, hv[q], v[(2 * p + 1) * 4 + q]);
                }
            }
        }
    }

    // z: naive butterfly
#pragma unroll
    for (int o = 16; o; o >>= 1)
#pragma unroll
        for (int p = 0; p < RPW / 2; p++) z2[p] = add2(z2[p], shfl2(z2[p], o));

    // v[32]: fully distributed butterfly -> lane l holds slot l
#pragma unroll
    for (int s = 0; s < 5; s++) {
        const int o = 16 >> s;
        const int nv = 32 >> s;
        const bool hi = (lane & o) != 0;
#pragma unroll
        for (int i = 0; i < nv / 2; i++) {
            ull send = hi ? v[i] : v[i + nv / 2];
            ull recv = shfl2(send, o);
            ull keep = hi ? v[i + nv / 2] : v[i];
            v[i] = add2(keep, recv);
        }
    }

    // lane l: r = l>>2, q = l&3; coalesced STG.64 across the warp
    {
        const int r = lane >> 2, q = lane & 3;
        ull zp = z2[r >> 1];
        float Z = (r & 1) ? hi2(zp) : lo2(zp);
        float invz = (Z > 0.f) ? 1.f / Z : 0.f;
        const int gi = k * NN + i0 + r;
        g_g4[gi * 4 + q] = pk(fmaxf(lo2(v[0]) * invz, 0.f),
                              fmaxf(hi2(v[0]) * invz, 0.f));
    }
}

// ---------------- head: fc1 split-K GEMM (128 d-chunks x 4 k-quarters), R12 form ----------------
#define FBLK 64
__global__ void __launch_bounds__(256) head_fc1_kernel(const float* __restrict__ fc1w) {
    __shared__ float gs[16][FBLK + 1];
    __shared__ float ws[FBLK][64];
    const int t = threadIdx.x;
    const int d0 = blockIdx.x * FBLK;
    const int k0 = blockIdx.y * 16;
    const float* gg = reinterpret_cast<const float*>(g_g4);

#pragma unroll
    for (int idx = t; idx < 16 * (FBLK / 4); idx += 256) {
        int k = idx / (FBLK / 4), v = idx % (FBLK / 4);
        float4 x = *reinterpret_cast<const float4*>(gg + (k0 + k) * (NN * DOUT) + d0 + 4 * v);
        gs[k][4 * v + 0] = x.x; gs[k][4 * v + 1] = x.y;
        gs[k][4 * v + 2] = x.z; gs[k][4 * v + 3] = x.w;
    }
    for (int idx = t; idx < FBLK * FC1D; idx += 256) {
        int d = idx / FC1D, c = idx % FC1D;
        ws[d][c] = fc1w[d0 * FC1D + idx];
    }
    __syncthreads();

    const int k = t & 15;
    const int cg = t >> 4;
    ull acc[2] = {0ull, 0ull};

#pragma unroll 8
    for (int d = 0; d < FBLK; d++) {
        ull g2 = bcast2(__float_as_uint(gs[k][d]));
        const ull* w2 = reinterpret_cast<const ull*>(&ws[d][cg * 4]);
        acc[0] = fma2(g2, w2[0], acc[0]);
        acc[1] = fma2(g2, w2[1], acc[1]);
    }

    float* dst = g_xp + (size_t)(blockIdx.x * 4 + blockIdx.y) * FC1D * 16;
    const int cbase = cg * 4;
#pragma unroll
    for (int q = 0; q < 2; q++) {
        int c = cbase + 2 * q;
        if (c < FC1D)     dst[c * 16 + k] = lo2(acc[q]);
        if (c + 1 < FC1D) dst[(c + 1) * 16 + k] = hi2(acc[q]);
    }
}

// ---------------- head_out: reduce partials + bias/relu + GEMV (R12 form) ----------------
__global__ void __launch_bounds__(256) head_out_kernel(const float* __restrict__ fc1b,
                                                       const float* __restrict__ outw,
                                                       const float* __restrict__ outb,
                                                       float* __restrict__ out) {
    __shared__ float part[4][FC1D];
    __shared__ float xs[FC1D];
    const int k = blockIdx.y;
    const int t = threadIdx.x;
    const int kq = k >> 4, kk = k & 15;

    if (t < 4 * FC1D) {
        const int c = t % FC1D, q = t / FC1D;
        float s = 0.f;
#pragma unroll 8
        for (int d = q * 32; d < q * 32 + 32; d++)
            s += g_xp[((size_t)(d * 4 + kq) * FC1D + c) * 16 + kk];
        part[q][c] = s;
    }
    __syncthreads();
    if (t < FC1D)
        xs[t] = fmaxf(part[0][t] + part[1][t] + part[2][t] + part[3][t] + fc1b[t], 0.f);
    __syncthreads();

    const int n = blockIdx.x * 256 + t;
    float s = outb[n];
#pragma unroll
    for (int c2 = 0; c2 < FC1D; c2++) s += xs[c2] * outw[c2 * NN + n];
    out[k * NN + n] = s;
}

// ---------------- launch ----------------
extern "C" void kernel_launch(void* const* d_in, const int* in_sizes, int n_in,
                              void* d_out, int out_size) {
    const float* X    = (const float*)d_in[0];
    const int*   adj  = (const int*)d_in[1];
    const float* W1   = (const float*)d_in[2];
    const float* a1   = (const float*)d_in[3];
    const float* W2   = (const float*)d_in[4];
    const float* a2   = (const float*)d_in[5];
    const float* fc1w = (const float*)d_in[6];
    const float* fc1b = (const float*)d_in[7];
    const float* outw = (const float*)d_in[8];
    const float* outb = (const float*)d_in[9];
    float* out = (float*)d_out;

    prologue_kernel<<<384, 256>>>(adj, X, W1, a1);
    {
        dim3 grid(NN / 64, KBATCH);    // 256 thr, 8 warps, 64 rows/block, 2 blocks/SM
        attn1_kernel<<<grid, 256>>>(W2, a2);
        attn2_kernel<<<grid, 256>>>();
    }
    {
        dim3 gridf((NN * DOUT) / FBLK, 4);   // 128 d-chunks x 4 k-quarters
        head_fc1_kernel<<<gridf, 256>>>(fc1w);
    }
    {
        dim3 grid(NN / 256, KBATCH);
        head_out_kernel<<<grid, 256>>>(fc1b, outw, outb, out);
    }
}